// round 5
// baseline (speedup 1.0000x reference)
#include <cuda_runtime.h>
#include <cstdint>

// Problem shapes (fixed by setup_inputs)
#define B      4
#define NC     1024
#define NF     8192

#define GD     32                      // grid cells per axis
#define NCELL  (GD * GD * GD)          // 32768
#define NT     (B * 2)                 // 8 tasks: (batch, direction)
#define H      0.25f
#define INVH   4.0f
#define ORIGIN (-4.0f)

#define TPB    256
#define NRED   148
#define CPT    (NCELL / TPB)           // cells per thread in scan = 128

// Scratch (allocation-free rule: __device__ globals)
__device__ int    g_count [NT * NCELL];
__device__ int    g_start [NT * (NCELL + 1)];
__device__ int    g_cursor[NT * NCELL];
__device__ float4 g_sorted[NT * NF];
__device__ float  g_minsq [NT * NF];
__device__ float  g_part  [NRED * 3];
__device__ unsigned int g_done;        // self-resetting -> graph-replay safe

__device__ __forceinline__ int clampi(int v, int lo, int hi) {
    return min(max(v, lo), hi);
}
__device__ __forceinline__ int cell_of(float c) {
    return clampi((int)floorf((c - ORIGIN) * INVH), 0, GD - 1);
}

// task t: b = t>>1, dir = t&1.
// dir 0: queries = ret_fine, DB = gt_fine   (d1 direction)
// dir 1: queries = gt_fine,  DB = ret_fine  (d2 direction)

// ---------------------------------------------------------------------------
__global__ void zero_kernel() {
    int i = blockIdx.x * blockDim.x + threadIdx.x;
    if (i < NT * NCELL) g_count[i] = 0;
}

// ---------------------------------------------------------------------------
__global__ void count_kernel(const float* __restrict__ X,   // ret_fine
                             const float* __restrict__ Y) { // gt_fine
    int gid = blockIdx.x * blockDim.x + threadIdx.x;        // [0, NT*NF)
    int t = gid >> 13;                  // / NF
    int i = gid & (NF - 1);
    int b = t >> 1, dir = t & 1;
    const float* DB = dir ? X : Y;
    const float* p  = DB + (b * NF + i) * 3;
    int c = (cell_of(p[2]) * GD + cell_of(p[1])) * GD + cell_of(p[0]);
    atomicAdd(&g_count[t * NCELL + c], 1);
}

// ---------------------------------------------------------------------------
// Per-task exclusive prefix sum over 32768 cell counts. 8 CTAs.
__global__ __launch_bounds__(TPB) void scan_kernel() {
    __shared__ int sc[TPB];
    const int t    = blockIdx.x;
    const int tid  = threadIdx.x;
    const int cbase = t * NCELL + tid * CPT;
    const int sbase = t * (NCELL + 1) + tid * CPT;

    // pass 1: per-thread segment sum (unrolled for MLP)
    int sum = 0;
#pragma unroll 8
    for (int c = 0; c < CPT; ++c) sum += g_count[cbase + c];

    // block exclusive scan of the 256 segment sums
    sc[tid] = sum;
    __syncthreads();
    for (int off = 1; off < TPB; off <<= 1) {
        int v = (tid >= off) ? sc[tid - off] : 0;
        __syncthreads();
        sc[tid] += v;
        __syncthreads();
    }
    int run = sc[tid] - sum;   // exclusive prefix

    // pass 2: write starts + cursors
#pragma unroll 8
    for (int c = 0; c < CPT; ++c) {
        int v = g_count[cbase + c];
        g_start [sbase + c] = run;
        g_cursor[cbase + c] = run;
        run += v;
    }
    if (tid == TPB - 1) g_start[t * (NCELL + 1) + NCELL] = run;  // sentinel = NF
}

// ---------------------------------------------------------------------------
__global__ void scatter_kernel(const float* __restrict__ X,
                               const float* __restrict__ Y) {
    int gid = blockIdx.x * blockDim.x + threadIdx.x;
    int t = gid >> 13;
    int i = gid & (NF - 1);
    int b = t >> 1, dir = t & 1;
    const float* DB = dir ? X : Y;
    const float* p  = DB + (b * NF + i) * 3;
    float p0 = p[0], p1 = p[1], p2 = p[2];
    int c = (cell_of(p2) * GD + cell_of(p1)) * GD + cell_of(p0);
    int pos = atomicAdd(&g_cursor[t * NCELL + c], 1);
    g_sorted[t * NF + pos] = make_float4(p0, p1, p2, 0.0f);
}

// ---------------------------------------------------------------------------
// Warp-per-query exact NN with doubling box radius.
// After searching the full (clamped) box of cell-radius k, every unseen DB
// point is >= k*H away (conservative also under boundary clamping), so we
// stop when best_sq <= (k*H)^2.
__global__ __launch_bounds__(TPB) void query_kernel(const float* __restrict__ X,
                                                    const float* __restrict__ Y) {
    const int gw   = blockIdx.x * (TPB / 32) + (threadIdx.x >> 5);  // [0, NT*NF)
    const int lane = threadIdx.x & 31;
    const int t  = gw >> 13;
    const int qi = gw & (NF - 1);
    const int b = t >> 1, dir = t & 1;

    const float* Q = dir ? Y : X;
    const float* qp = Q + (b * NF + qi) * 3;
    const float qx = qp[0], qy = qp[1], qz = qp[2];
    const int cx = cell_of(qx), cy = cell_of(qy), cz = cell_of(qz);

    const int sb = t * (NCELL + 1);
    const float4* __restrict__ pts = g_sorted + t * NF;

    float best = 3.0e38f;
    int k = 1;
    for (;;) {
        const int w = 2 * k + 1;
        const int x0 = max(cx - k, 0);
        const int x1 = min(cx + k, GD - 1);
        const int nrows = w * w;

        for (int base = 0; base < nrows; base += 32) {
            // lane-parallel fetch of this batch's row ranges
            int s = 0, e = 0;
            int r = base + lane;
            if (r < nrows) {
                int dz = r / w - k;
                int dy = r - (dz + k) * w - k;
                int yy = cy + dy, zz = cz + dz;
                if (yy >= 0 && yy < GD && zz >= 0 && zz < GD) {
                    int crow = (zz * GD + yy) * GD;
                    s = g_start[sb + crow + x0];
                    e = g_start[sb + crow + x1 + 1];
                }
            }
            const int nr = min(nrows - base, 32);
            for (int rr = 0; rr < nr; ++rr) {
                const int ss = __shfl_sync(0xffffffffu, s, rr);
                const int ee = __shfl_sync(0xffffffffu, e, rr);
                for (int j = ss + lane; j < ee; j += 32) {
                    float4 p = pts[j];
                    float d0 = p.x - qx;
                    float d1 = p.y - qy;
                    float d2 = p.z - qz;
                    best = fminf(best, fmaf(d0, d0, fmaf(d1, d1, d2 * d2)));
                }
            }
        }

        // warp-wide min, uniform across lanes
#pragma unroll
        for (int off = 16; off; off >>= 1)
            best = fminf(best, __shfl_xor_sync(0xffffffffu, best, off));

        const float bound = (float)k * H;
        if (best <= bound * bound || k >= GD) break;
        k = min(2 * k, GD);   // 1,2,4,8,16,32 (32 >= 31 covers the whole grid)
    }

    if (lane == 0) g_minsq[t * NF + qi] = best;
}

// ---------------------------------------------------------------------------
// Fold: sqrt of min-squared dists + coarse L2; last block combines + writes.
__global__ __launch_bounds__(TPB) void reduce_kernel(const float* __restrict__ rc,
                                                     const float* __restrict__ gc,
                                                     float* __restrict__ out) {
    __shared__ float sbuf[TPB];
    __shared__ bool  sLast;
    const int tid    = threadIdx.x;
    const int gstart = blockIdx.x * TPB + tid;
    const int stride = gridDim.x * TPB;

    float sf = 0.0f, sc = 0.0f;
    for (int i = gstart; i < NT * NF; i += stride)
        sf += sqrtf(g_minsq[i]);
    for (int p = gstart; p < B * NC; p += stride) {
        float d0 = rc[p * 3 + 0] - gc[p * 3 + 0];
        float d1 = rc[p * 3 + 1] - gc[p * 3 + 1];
        float d2 = rc[p * 3 + 2] - gc[p * 3 + 2];
        sc += sqrtf(fmaf(d0, d0, fmaf(d1, d1, d2 * d2)));
    }

    float vals[2] = {sf, sc};
#pragma unroll
    for (int kk = 0; kk < 2; ++kk) {
        sbuf[tid] = vals[kk];
        __syncthreads();
        for (int off = TPB / 2; off > 0; off >>= 1) {
            if (tid < off) sbuf[tid] += sbuf[tid + off];
            __syncthreads();
        }
        if (tid == 0) g_part[blockIdx.x * 3 + kk] = sbuf[0];
        __syncthreads();
    }

    __threadfence();
    if (tid == 0) sLast = (atomicAdd(&g_done, 1u) == gridDim.x - 1);
    __syncthreads();
    if (!sLast) return;

    float r1 = 0.0f, r2 = 0.0f;
    for (int c = tid; c < NRED; c += TPB) {
        r1 += g_part[c * 3 + 0];
        r2 += g_part[c * 3 + 1];
    }
    float v2[2] = {r1, r2};
    float acc[2];
#pragma unroll
    for (int kk = 0; kk < 2; ++kk) {
        sbuf[tid] = v2[kk];
        __syncthreads();
        for (int off = TPB / 2; off > 0; off >>= 1) {
            if (tid < off) sbuf[tid] += sbuf[tid + off];
            __syncthreads();
        }
        acc[kk] = sbuf[0];
        __syncthreads();
    }
    if (tid == 0) {
        out[0] = acc[1] / (float)(B * NC);          // loss_coarse
        out[1] = acc[0] / (float)(2 * B * NF);      // loss_fine = 0.5*(m1+m2)
        g_done = 0;                                 // reset for next replay
    }
}

// ---------------------------------------------------------------------------
extern "C" void kernel_launch(void* const* d_in, const int* in_sizes, int n_in,
                              void* d_out, int out_size) {
    const float* ret_coarse = (const float*)d_in[0];
    const float* ret_fine   = (const float*)d_in[1];
    const float* gt_fine    = (const float*)d_in[2];
    const float* gt_coarse  = (const float*)d_in[3];
    float* out = (float*)d_out;

    zero_kernel   <<<(NT * NCELL + TPB - 1) / TPB, TPB>>>();
    count_kernel  <<<(NT * NF) / TPB, TPB>>>(ret_fine, gt_fine);
    scan_kernel   <<<NT, TPB>>>();
    scatter_kernel<<<(NT * NF) / TPB, TPB>>>(ret_fine, gt_fine);
    query_kernel  <<<(NT * NF) / (TPB / 32), TPB>>>(ret_fine, gt_fine);
    reduce_kernel <<<NRED, TPB>>>(ret_coarse, gt_coarse, out);
}

// round 6
// speedup vs baseline: 2.3086x; 2.3086x over previous
#include <cuda_runtime.h>
#include <cstdint>

// Problem shapes (fixed by setup_inputs)
#define B      4
#define NC     1024
#define NF     8192

#define TILE   128          // rows per tile AND cols per CTA
#define TPB    256          // 16x16 threads
#define ROWSPLIT 4          // CTAs splitting the row dimension
#define NRED   148          // reduction CTAs

#define INF_BITS 0x7f800000u
#define PADW   18           // sPart row pad: conflict-free STS

typedef unsigned long long u64;

// Scratch (allocation-free rule: __device__ globals)
__device__ unsigned int g_min1[B * NF];   // min over gt   for each ret_fine point (rows)
__device__ unsigned int g_min2[B * NF];   // min over ret  for each gt_fine  point (cols)
__device__ float        g_part[NRED * 3];
__device__ unsigned int g_done;           // self-resetting -> graph-replay safe

// ---- packed f32x2 helpers (sm_103a) ---------------------------------------
__device__ __forceinline__ u64 pk(float lo, float hi) {
    u64 r; asm("mov.b64 %0, {%1, %2};" : "=l"(r) : "f"(lo), "f"(hi)); return r;
}
__device__ __forceinline__ void upk(float& lo, float& hi, u64 v) {
    asm("mov.b64 {%0, %1}, %2;" : "=f"(lo), "=f"(hi) : "l"(v));
}
__device__ __forceinline__ u64 fma2(u64 a, u64 b, u64 c) {
    u64 d; asm("fma.rn.f32x2 %0, %1, %2, %3;" : "=l"(d) : "l"(a), "l"(b), "l"(c)); return d;
}
__device__ __forceinline__ u64 add2(u64 a, u64 b) {
    u64 d; asm("add.rn.f32x2 %0, %1, %2;" : "=l"(d) : "l"(a), "l"(b)); return d;
}

// ---------------------------------------------------------------------------
// Vectorized init: 2*B*NF uints = 16K uint4 stores.
__global__ void init_mins_kernel() {
    int i = blockIdx.x * blockDim.x + threadIdx.x;
    uint4 v = make_uint4(INF_BITS, INF_BITS, INF_BITS, INF_BITS);
    if (i < (B * NF) / 4) {
        ((uint4*)g_min1)[i] = v;
        ((uint4*)g_min2)[i] = v;
    }
    if (i == 0) g_done = 0;   // idempotent (reduce resets it too)
}

// ---------------------------------------------------------------------------
// Fused pairwise-distance + dual min-reduction (R2 structure, RS=4).
// grid: (NF/TILE, ROWSPLIT, B), block 16x16, micro-tile 8x8 (cols packed 2-wide).
// X = ret_fine (rows -> g_min1), Y = gt_fine (cols -> g_min2).
__global__ __launch_bounds__(TPB, 4) void chamfer_kernel(const float* __restrict__ X,
                                                         const float* __restrict__ Y) {
    __shared__ float4       sX[TILE];          // streamed row tile (x,y,z,|x|^2); Y staging 1st
    __shared__ float        sPart[TILE][PADW]; // per-(row, tx) partial row mins
    __shared__ unsigned int sCol[TILE];        // CTA col mins

    const int tid = threadIdx.x;
    const int tx  = tid & 15;              // 16 col-thread groups (8 cols each)
    const int ty  = tid >> 4;              // 16 row-thread groups (8 rows each)
    const int b   = blockIdx.z;
    const int colbase = blockIdx.x * TILE;
    const int row0    = blockIdx.y * (NF / ROWSPLIT);
    const int nTiles  = (NF / ROWSPLIT) / TILE;   // 16

    // Stage Y tile through sX: (-2x, -2y, -2z, |y|^2)
    if (tid < TILE) {
        int jg = b * NF + colbase + tid;
        float y0 = Y[jg * 3 + 0];
        float y1 = Y[jg * 3 + 1];
        float y2 = Y[jg * 3 + 2];
        sX[tid]  = make_float4(-2.0f * y0, -2.0f * y1, -2.0f * y2,
                               fmaf(y0, y0, fmaf(y1, y1, y2 * y2)));
        sCol[tid] = INF_BITS;
    }
    __syncthreads();

    // Persistent packed column registers: 8 cols as 4 f32x2 groups
    u64 ya[4], yb[4], yc[4], yw[4];
    float cm[8];
#pragma unroll
    for (int g = 0; g < 4; ++g) {
        float4 p = sX[tx * 8 + 2 * g];
        float4 q = sX[tx * 8 + 2 * g + 1];
        ya[g] = pk(p.x, q.x);
        yb[g] = pk(p.y, q.y);
        yc[g] = pk(p.z, q.z);
        yw[g] = pk(p.w, q.w);
        cm[2 * g]     = __int_as_float(0x7f800000);
        cm[2 * g + 1] = __int_as_float(0x7f800000);
    }
    __syncthreads();   // done staging Y through sX

    for (int t = 0; t < nTiles; ++t) {
        const int r0 = row0 + t * TILE;
        if (tid < TILE) {
            int ig = b * NF + r0 + tid;
            float x0 = X[ig * 3 + 0];
            float x1 = X[ig * 3 + 1];
            float x2 = X[ig * 3 + 2];
            sX[tid]  = make_float4(x0, x1, x2, fmaf(x0, x0, fmaf(x1, x1, x2 * x2)));
        }
        __syncthreads();   // sync A

#pragma unroll
        for (int i = 0; i < 8; ++i) {
            const float4 xp = sX[ty * 8 + i];
            const u64 bx = pk(xp.x, xp.x);
            const u64 by = pk(xp.y, xp.y);
            const u64 bz = pk(xp.z, xp.z);
            const u64 bw = pk(xp.w, xp.w);
            float rml = __int_as_float(0x7f800000);
            float rmh = __int_as_float(0x7f800000);
#pragma unroll
            for (int g = 0; g < 4; ++g) {
                // d = |x|^2 + |y|^2 - 2 x.y   (y pre-scaled by -2, |y|^2 folded)
                u64 e = add2(yw[g], bw);
                e = fma2(yc[g], bz, e);
                e = fma2(yb[g], by, e);
                e = fma2(ya[g], bx, e);
                float dl, dh;
                upk(dl, dh, e);
                rml = fminf(rml, dl);
                rmh = fminf(rmh, dh);
                cm[2 * g]     = fminf(cm[2 * g],     dl);
                cm[2 * g + 1] = fminf(cm[2 * g + 1], dh);
            }
            sPart[ty * 8 + i][tx] = fminf(rml, rmh);
        }
        __syncthreads();   // sync B

        if (tid < TILE) {
            float m = sPart[tid][0];
#pragma unroll
            for (int c = 1; c < 16; ++c) m = fminf(m, sPart[tid][c]);
            atomicMin(&g_min1[b * NF + r0 + tid], __float_as_uint(fmaxf(m, 0.0f)));
        }
        // loop-top sync A orders sPart rewrite after these reads
    }

    // Flush column mins once per CTA
#pragma unroll
    for (int j = 0; j < 8; ++j)
        atomicMin(&sCol[tx * 8 + j], __float_as_uint(fmaxf(cm[j], 0.0f)));
    __syncthreads();
    if (tid < TILE)
        atomicMin(&g_min2[b * NF + colbase + tid], sCol[tid]);
}

// ---------------------------------------------------------------------------
// Partial sums (sqrt of min arrays + coarse L2) with fused last-block final.
__global__ __launch_bounds__(TPB) void reduce_kernel(const float* __restrict__ rc,
                                                     const float* __restrict__ gc,
                                                     float* __restrict__ out) {
    __shared__ float sbuf[TPB];
    __shared__ bool  sLast;
    const int tid    = threadIdx.x;
    const int gstart = blockIdx.x * TPB + tid;
    const int stride = gridDim.x * TPB;

    float s1 = 0.0f, s2 = 0.0f, sc = 0.0f;
    for (int i = gstart; i < B * NF; i += stride)
        s1 += sqrtf(__uint_as_float(g_min1[i]));
    for (int i = gstart; i < B * NF; i += stride)
        s2 += sqrtf(__uint_as_float(g_min2[i]));
    for (int p = gstart; p < B * NC; p += stride) {
        float d0 = rc[p * 3 + 0] - gc[p * 3 + 0];
        float d1 = rc[p * 3 + 1] - gc[p * 3 + 1];
        float d2 = rc[p * 3 + 2] - gc[p * 3 + 2];
        sc += sqrtf(fmaf(d0, d0, fmaf(d1, d1, d2 * d2)));
    }

    float vals[3] = {s1, s2, sc};
#pragma unroll
    for (int k = 0; k < 3; ++k) {
        sbuf[tid] = vals[k];
        __syncthreads();
        for (int off = TPB / 2; off > 0; off >>= 1) {
            if (tid < off) sbuf[tid] += sbuf[tid + off];
            __syncthreads();
        }
        if (tid == 0) g_part[blockIdx.x * 3 + k] = sbuf[0];
        __syncthreads();
    }

    // Last block combines (deterministic fixed order), resets g_done for replay.
    __threadfence();
    if (tid == 0) sLast = (atomicAdd(&g_done, 1u) == gridDim.x - 1);
    __syncthreads();
    if (!sLast) return;

    float r1 = 0.0f, r2 = 0.0f, r3 = 0.0f;
    for (int c = tid; c < NRED; c += TPB) {
        r1 += g_part[c * 3 + 0];
        r2 += g_part[c * 3 + 1];
        r3 += g_part[c * 3 + 2];
    }
    float v2[3] = {r1, r2, r3};
    float acc[3];
#pragma unroll
    for (int k = 0; k < 3; ++k) {
        sbuf[tid] = v2[k];
        __syncthreads();
        for (int off = TPB / 2; off > 0; off >>= 1) {
            if (tid < off) sbuf[tid] += sbuf[tid + off];
            __syncthreads();
        }
        acc[k] = sbuf[0];
        __syncthreads();
    }
    if (tid == 0) {
        const float invBN = 1.0f / (float)(B * NF);
        out[0] = acc[2] / (float)(B * NC);                   // loss_coarse
        out[1] = 0.5f * (acc[0] * invBN + acc[1] * invBN);   // loss_fine
        g_done = 0;                                          // reset for next replay
    }
}

// ---------------------------------------------------------------------------
extern "C" void kernel_launch(void* const* d_in, const int* in_sizes, int n_in,
                              void* d_out, int out_size) {
    const float* ret_coarse = (const float*)d_in[0];
    const float* ret_fine   = (const float*)d_in[1];
    const float* gt_fine    = (const float*)d_in[2];
    const float* gt_coarse  = (const float*)d_in[3];
    float* out = (float*)d_out;

    init_mins_kernel<<<((B * NF) / 4 + TPB - 1) / TPB, TPB>>>();

    dim3 grid(NF / TILE, ROWSPLIT, B);   // (64, 4, 4) = 1024 CTAs
    chamfer_kernel<<<grid, TPB>>>(ret_fine, gt_fine);

    reduce_kernel<<<NRED, TPB>>>(ret_coarse, gt_coarse, out);
}